// round 10
// baseline (speedup 1.0000x reference)
#include <cuda_runtime.h>
#include <cuda_fp16.h>
#include <math.h>
#include <stdint.h>

#define T_SEQ  2048
#define BATCH  2
#define DMODEL 2048
#define NH     16
#define DHEAD  128
#define DCAT   128
#define LOG2E  1.44269504088896340736f

// ---------------- scratch (device globals: allocation-free) ----------------
__device__ float  g_Qcat[(size_t)BATCH * NH * T_SEQ * DCAT];
__device__ float  g_Kcat[(size_t)BATCH * NH * T_SEQ * DCAT];
__device__ __half g_Qh[(size_t)BATCH * NH * T_SEQ * DCAT];
__device__ __half g_Ql[(size_t)BATCH * NH * T_SEQ * DCAT];
__device__ __half g_Kh[(size_t)BATCH * NH * T_SEQ * DCAT];
__device__ __half g_Kl[(size_t)BATCH * NH * T_SEQ * DCAT];
__device__ __half g_Vh[(size_t)BATCH * NH * DHEAD * T_SEQ];   // [bh][d][t]
__device__ __half g_Oh[(size_t)BATCH * T_SEQ * DMODEL];       // attention out (fp16)
__device__ __half g_WTh[4u * 2048u * 1024u + 2u * 2048u * 2048u]; // fp16 transposed weights
__device__ __half g_Xh [(size_t)BATCH * T_SEQ * DMODEL];      // fp16 x

// ---------------- helpers ----------------
__device__ __forceinline__ uint32_t smem_u32(const void* p) {
    uint32_t a;
    asm("{ .reg .u64 t; cvta.to.shared.u64 t, %1; cvt.u32.u64 %0, t; }" : "=r"(a) : "l"(p));
    return a;
}
__device__ __forceinline__ void cp16(uint32_t dst, const void* src) {
    asm volatile("cp.async.cg.shared.global [%0], [%1], 16;" :: "r"(dst), "l"(src) : "memory");
}
__device__ __forceinline__ void mma_f16(float c[4], const uint32_t a[4], const uint32_t b[2]) {
    asm volatile(
        "mma.sync.aligned.m16n8k16.row.col.f32.f16.f16.f32 "
        "{%0,%1,%2,%3}, {%4,%5,%6,%7}, {%8,%9}, {%0,%1,%2,%3};"
        : "+f"(c[0]), "+f"(c[1]), "+f"(c[2]), "+f"(c[3])
        : "r"(a[0]), "r"(a[1]), "r"(a[2]), "r"(a[3]), "r"(b[0]), "r"(b[1]));
}
// fast exp2 on the FMA pipe (input s <= 0), rel err ~2e-8
__device__ __forceinline__ float fexp2(float s) {
    s = fmaxf(s, -126.f);
    float fl = floorf(s);
    float f = s - fl;
    float p = 1.33336498402e-3f;
    p = fmaf(p, f, 9.81094251585e-3f);
    p = fmaf(p, f, 5.54906469989e-2f);
    p = fmaf(p, f, 2.40230073528e-1f);
    p = fmaf(p, f, 6.93146984780e-1f);
    p = fmaf(p, f, 1.0f);
    int ei = (int)fl;
    return p * __int_as_float((ei + 127) << 23);
}

// ---------------- elementwise fp16 convert of x ----------------
__global__ void round_f16_kernel(const float* __restrict__ in, __half* __restrict__ out)
{
    int i = blockIdx.x * 256 + threadIdx.x;
    float4 v = ((const float4*)in)[i];
    __half2 h0 = __floats2half2_rn(v.x, v.y);
    __half2 h1 = __floats2half2_rn(v.z, v.w);
    ((__half2*)out)[2 * i]     = h0;
    ((__half2*)out)[2 * i + 1] = h1;
}

// ---------------- weight transpose + fp16 round: WT[n][k] = h(W[k][n]) ----------------
__global__ void transpose_kernel(const float* __restrict__ W, __half* __restrict__ WT, int N)
{
    __shared__ float ts[32][33];
    int n0 = blockIdx.x * 32, k0 = blockIdx.y * 32;
    int x = threadIdx.x, y = threadIdx.y;
#pragma unroll
    for (int i = 0; i < 4; i++)
        ts[y + 8 * i][x] = W[(size_t)(k0 + y + 8 * i) * N + n0 + x];
    __syncthreads();
#pragma unroll
    for (int i = 0; i < 4; i++)
        WT[(size_t)(n0 + y + 8 * i) * 2048 + k0 + x] = __float2half_rn(ts[x][y + 8 * i]);
}

__global__ void transpose4_kernel(const float* __restrict__ W0, const float* __restrict__ W1,
                                  const float* __restrict__ W2, const float* __restrict__ W3,
                                  __half* __restrict__ WT)
{
    __shared__ float ts[32][33];
    const float* W = (blockIdx.z == 0) ? W0 : (blockIdx.z == 1) ? W1 :
                     (blockIdx.z == 2) ? W2 : W3;
    __half* dst = WT + (size_t)blockIdx.z * 2048u * 1024u;
    int n0 = blockIdx.x * 32, k0 = blockIdx.y * 32;
    int x = threadIdx.x, y = threadIdx.y;
#pragma unroll
    for (int i = 0; i < 4; i++)
        ts[y + 8 * i][x] = W[(size_t)(k0 + y + 8 * i) * 1024 + n0 + x];
    __syncthreads();
#pragma unroll
    for (int i = 0; i < 4; i++)
        dst[(size_t)(n0 + y + 8 * i) * 2048 + k0 + x] = __float2half_rn(ts[x][y + 8 * i]);
}

// ---------------- fp16 HMMA GEMM (128x128 tile, K-chunk 32, 3-stage cp.async) -------
// smem stage: A 128 rows x 40 halves (pad) + B 128 rows x 40 halves = 20480 B
// modes: 0 = fused QK projections (fp32 out0/out1); 1 = V -> fp16 transposed; 2 = plain fp32
#define HSTG_H   10240           // halves per stage
#define HSTG_B   20480           // bytes per stage
#define GEMM_SMEM (3 * HSTG_B)   // 61440 B -> 2+ CTAs/SM

__global__ __launch_bounds__(256, 2)
void gemm_mma(const __half* __restrict__ A, const __half* __restrict__ BT,
              float* __restrict__ out0, float* __restrict__ out1,
              __half* __restrict__ outh, int mode)
{
    extern __shared__ __half smh[];
    const uint32_t sbase = smem_u32(smh);
    const uint32_t* s32 = (const uint32_t*)smh;

    const int tid  = threadIdx.x;
    const int wid  = tid >> 5;
    const int lane = tid & 31;
    const int wm = wid & 1;
    const int wn = wid >> 1;
    const int g  = lane >> 2;
    const int tg = lane & 3;

    const int bm = blockIdx.y * 128;
    const int bn = blockIdx.x * 128;

    const __half* Ab = A  + (size_t)bm * 2048;
    const __half* Bb = BT + (size_t)bn * 2048;

    auto load_tile = [&](int kt) {
        int s = kt % 3;
        uint32_t aB = sbase + s * HSTG_B;
        uint32_t bB = aB + HSTG_B / 2;
        int k0 = kt * 32;
#pragma unroll
        for (int j = 0; j < 2; j++) {
            int idx = tid + 256 * j;
            int row = idx >> 2, c = idx & 3;
            cp16(aB + row * 80 + c * 16, Ab + (size_t)row * 2048 + k0 + c * 8);
        }
#pragma unroll
        for (int j = 0; j < 2; j++) {
            int idx = tid + 256 * j;
            int row = idx >> 2, c = idx & 3;
            cp16(bB + row * 80 + c * 16, Bb + (size_t)row * 2048 + k0 + c * 8);
        }
    };

    float c[4][4][4];
#pragma unroll
    for (int mt = 0; mt < 4; mt++)
#pragma unroll
        for (int nt = 0; nt < 4; nt++)
#pragma unroll
            for (int i = 0; i < 4; i++) c[mt][nt][i] = 0.f;

    load_tile(0); asm volatile("cp.async.commit_group;" ::: "memory");
    load_tile(1); asm volatile("cp.async.commit_group;" ::: "memory");

    for (int it = 0; it < 64; it++) {
        asm volatile("cp.async.wait_group 1;" ::: "memory");
        __syncthreads();

        if (it + 2 < 64) load_tile(it + 2);
        asm volatile("cp.async.commit_group;" ::: "memory");

        const int aH = (it % 3) * HSTG_H;       // half-index of A stage
        const int bH = aH + HSTG_H / 2;

#pragma unroll
        for (int ks = 0; ks < 2; ks++) {
            uint32_t af[4][4], bf[4][2];
#pragma unroll
            for (int mt = 0; mt < 4; mt++) {
                int H = aH + (wm * 64 + mt * 16 + g) * 40 + ks * 16 + 2 * tg;
                af[mt][0] = s32[H >> 1];
                af[mt][1] = s32[(H + 320) >> 1];   // +8 rows
                af[mt][2] = s32[(H + 8) >> 1];
                af[mt][3] = s32[(H + 328) >> 1];
            }
#pragma unroll
            for (int nt = 0; nt < 4; nt++) {
                int H = bH + (wn * 32 + nt * 8 + g) * 40 + ks * 16 + 2 * tg;
                bf[nt][0] = s32[H >> 1];
                bf[nt][1] = s32[(H + 8) >> 1];
            }
#pragma unroll
            for (int mt = 0; mt < 4; mt++)
#pragma unroll
                for (int nt = 0; nt < 4; nt++)
                    mma_f16(c[mt][nt], af[mt], bf[nt]);
        }
    }

    // ---------------- epilogue ----------------
#pragma unroll
    for (int mt = 0; mt < 4; mt++) {
        int m0 = bm + wm * 64 + mt * 16 + g;
        int m1 = m0 + 8;
        int b0 = m0 >> 11, t0 = m0 & 2047;
        int b1 = m1 >> 11, t1 = m1 & 2047;
#pragma unroll
        for (int nt = 0; nt < 4; nt++) {
            int col = bn + wn * 32 + nt * 8 + tg * 2;
            if (mode == 0) {
                int mat = col >> 10;
                float* dst = (mat & 1) ? out1 : out0;
                int ds = (mat >= 2) ? 64 : 0;
                int h = (col >> 6) & 15, d = col & 63;
                size_t i0 = (((size_t)b0 * NH + h) * T_SEQ + t0) * DCAT + ds + d;
                size_t i1 = (((size_t)b1 * NH + h) * T_SEQ + t1) * DCAT + ds + d;
                *(float2*)&dst[i0] = make_float2(c[mt][nt][0], c[mt][nt][1]);
                *(float2*)&dst[i1] = make_float2(c[mt][nt][2], c[mt][nt][3]);
            } else if (mode == 1) {
                int h = col >> 7, d = col & 127;
                size_t base0 = ((size_t)(b0 * NH + h) * 128 + d) * 2048;
                size_t base1 = ((size_t)(b1 * NH + h) * 128 + d) * 2048;
                outh[base0 + t0]        = __float2half_rn(c[mt][nt][0]);
                outh[base0 + 2048 + t0] = __float2half_rn(c[mt][nt][1]);
                outh[base1 + t1]        = __float2half_rn(c[mt][nt][2]);
                outh[base1 + 2048 + t1] = __float2half_rn(c[mt][nt][3]);
            } else {
                size_t i0 = ((size_t)(b0 * T_SEQ + t0)) * 2048 + col;
                size_t i1 = ((size_t)(b1 * T_SEQ + t1)) * 2048 + col;
                *(float2*)&out0[i0] = make_float2(c[mt][nt][0], c[mt][nt][1]);
                *(float2*)&out0[i1] = make_float2(c[mt][nt][2], c[mt][nt][3]);
            }
        }
    }
}

// ---------------- RoPE + gate folding -> split fp16 Q/K ----------------
__global__ void rope_gate_kernel(const float* __restrict__ Qcat, const float* __restrict__ Kcat,
                                 __half* __restrict__ Qh, __half* __restrict__ Ql,
                                 __half* __restrict__ Kh, __half* __restrict__ Kl,
                                 const float* __restrict__ gate_logit,
                                 const int* __restrict__ pos_off)
{
    int row  = blockIdx.x * 4 + (threadIdx.x >> 5);
    int lane = threadIdx.x & 31;

    int t = row % T_SEQ;
    int h = (row / T_SEQ) % NH;

    float g = 1.f / (1.f + expf(-gate_logit[h]));
    float qs_scale = 2.f * g * 0.125f * LOG2E;
    float qg_scale = (2.f - 2.f * g) * 0.125f * LOG2E;

    float freq = powf(10000.f, -(float)lane / 32.f);
    float ang  = (float)(t + pos_off[0]) * freq;
    float c = cosf(ang), s = sinf(ang);

    const float* qp = Qcat + (size_t)row * DCAT;
    const float* kp = Kcat + (size_t)row * DCAT;
    size_t ob = (size_t)row * DCAT;

    auto wsplit = [&](__half* ah, __half* al, int d, float v) {
        __half hh = __float2half_rn(v);
        ah[ob + d] = hh;
        al[ob + d] = __float2half_rn(v - __half2float(hh));
    };

    wsplit(Qh, Ql, lane,      qp[lane]      * qs_scale);
    wsplit(Qh, Ql, lane + 32, qp[lane + 32] * qs_scale);
    float x1 = qp[64 + lane], x2 = qp[96 + lane];
    wsplit(Qh, Ql, 64 + lane, (x1 * c - x2 * s) * qg_scale);
    wsplit(Qh, Ql, 96 + lane, (x2 * c + x1 * s) * qg_scale);

    wsplit(Kh, Kl, lane,      kp[lane]);
    wsplit(Kh, Kl, lane + 32, kp[lane + 32]);
    float k1 = kp[64 + lane], k2 = kp[96 + lane];
    wsplit(Kh, Kl, 64 + lane, k1 * c - k2 * s);
    wsplit(Kh, Kl, 96 + lane, k2 * c + k1 * s);
}

// ---------------- fp16 mma flash attention (register P, poly exp2) ----------------
#define QH_O 0
#define QL_O 17408
#define KH_O 34816
#define KL_O 43520
#define VH_O 52224
#define SMEM_FLASH (61440 * 2)

__global__ __launch_bounds__(256, 1)
void flash_mma(const __half* __restrict__ Qh, const __half* __restrict__ Ql,
               const __half* __restrict__ Kh, const __half* __restrict__ Kl,
               const __half* __restrict__ Vh, __half* __restrict__ Og)
{
    extern __shared__ __half smh[];
    const uint32_t sb = smem_u32(smh);
    const uint32_t* s32 = (const uint32_t*)smh;

    const int qi = gridDim.x - 1 - blockIdx.x;   // longest-first
    const int bh = blockIdx.y;
    const int q0 = qi * 128;

    const int tid  = threadIdx.x;
    const int lane = tid & 31;
    const int g  = lane >> 2;
    const int tg = lane & 3;
    const int m0 = (tid >> 5) * 16;

    const __half* Qbh = Qh + ((size_t)bh * T_SEQ + q0) * DCAT;
    const __half* Qbl = Ql + ((size_t)bh * T_SEQ + q0) * DCAT;
    const __half* Kbh = Kh + (size_t)bh * T_SEQ * DCAT;
    const __half* Kbl = Kl + (size_t)bh * T_SEQ * DCAT;
    const __half* Vb  = Vh + (size_t)bh * DHEAD * T_SEQ;

    auto loadK = [&](int kt) {
        const __half* sh = Kbh + (size_t)kt * 64 * DCAT;
        const __half* sl = Kbl + (size_t)kt * 64 * DCAT;
#pragma unroll
        for (int j = 0; j < 4; j++) {
            int i = tid + 256 * j;
            int r = i >> 4, c8 = i & 15;
            cp16(sb + (KH_O + r * 136 + c8 * 8) * 2, sh + r * DCAT + c8 * 8);
        }
#pragma unroll
        for (int j = 0; j < 4; j++) {
            int i = tid + 256 * j;
            int r = i >> 4, c8 = i & 15;
            cp16(sb + (KL_O + r * 136 + c8 * 8) * 2, sl + r * DCAT + c8 * 8);
        }
    };
    auto loadV = [&](int kt) {
#pragma unroll
        for (int j = 0; j < 4; j++) {
            int i = tid + 256 * j;
            int d = i >> 3, c8 = i & 7;
            cp16(sb + (VH_O + d * 72 + c8 * 8) * 2, Vb + (size_t)d * T_SEQ + kt * 64 + c8 * 8);
        }
    };

#pragma unroll
    for (int j = 0; j < 8; j++) {
        int i = tid + 256 * j;
        int r = i >> 4, c8 = i & 15;
        cp16(sb + (QH_O + r * 136 + c8 * 8) * 2, Qbh + (size_t)r * DCAT + c8 * 8);
    }
#pragma unroll
    for (int j = 0; j < 8; j++) {
        int i = tid + 256 * j;
        int r = i >> 4, c8 = i & 15;
        cp16(sb + (QL_O + r * 136 + c8 * 8) * 2, Qbl + (size_t)r * DCAT + c8 * 8);
    }
    loadK(0);
    asm volatile("cp.async.commit_group;" ::: "memory");
    loadV(0);
    asm volatile("cp.async.commit_group;" ::: "memory");

    float of[16][4];
#pragma unroll
    for (int nt = 0; nt < 16; nt++)
#pragma unroll
        for (int i = 0; i < 4; i++) of[nt][i] = 0.f;

    float mrun1 = -1e30f, mrun2 = -1e30f;
    float lrun1 = 0.f,    lrun2 = 0.f;

    const int nkt = 2 * (qi + 1);

    for (int kt = 0; kt < nkt; kt++) {
        const int k0 = kt * 64;

        asm volatile("cp.async.wait_group 1;" ::: "memory");
        __syncthreads();

        // ---- S = Q K^T : fp16 3-term split ----
        float sc[8][4];
#pragma unroll
        for (int nt = 0; nt < 8; nt++)
#pragma unroll
            for (int i = 0; i < 4; i++) sc[nt][i] = 0.f;

#pragma unroll
        for (int ks = 0; ks < 8; ks++) {
            int H  = (m0 + g) * 136 + ks * 16 + 2 * tg;
            int H8 = H + 8 * 136;
            uint32_t ah[4] = { s32[(QH_O + H) >> 1], s32[(QH_O + H8) >> 1],
                               s32[(QH_O + H + 8) >> 1], s32[(QH_O + H8 + 8) >> 1] };
            uint32_t al[4] = { s32[(QL_O + H) >> 1], s32[(QL_O + H8) >> 1],
                               s32[(QL_O + H + 8) >> 1], s32[(QL_O + H8 + 8) >> 1] };
#pragma unroll
            for (int nt = 0; nt < 8; nt++) {
                int KB = (nt * 8 + g) * 136 + ks * 16 + 2 * tg;
                uint32_t bh2[2] = { s32[(KH_O + KB) >> 1], s32[(KH_O + KB + 8) >> 1] };
                uint32_t bl2[2] = { s32[(KL_O + KB) >> 1], s32[(KL_O + KB + 8) >> 1] };
                mma_f16(sc[nt], ah, bh2);
                mma_f16(sc[nt], al, bh2);
                mma_f16(sc[nt], ah, bl2);
            }
        }
        __syncthreads();
        if (kt + 1 < nkt) loadK(kt + 1);
        asm volatile("cp.async.commit_group;" ::: "memory");

        // ---- register softmax ----
        const int gr1 = q0 + m0 + g, gr2 = gr1 + 8;
        float mx1 = mrun1, mx2 = mrun2;
#pragma unroll
        for (int nt = 0; nt < 8; nt++) {
            int gc = k0 + nt * 8 + 2 * tg;
            if (gc     > gr1) sc[nt][0] = -1e30f;
            if (gc + 1 > gr1) sc[nt][1] = -1e30f;
            if (gc     > gr2) sc[nt][2] = -1e30f;
            if (gc + 1 > gr2) sc[nt][3] = -1e30f;
            mx1 = fmaxf(mx1, fmaxf(sc[nt][0], sc[nt][1]));
            mx2 = fmaxf(mx2, fmaxf(sc[nt][2], sc[nt][3]));
        }
        mx1 = fmaxf(mx1, __shfl_xor_sync(0xffffffffu, mx1, 1));
        mx1 = fmaxf(mx1, __shfl_xor_sync(0xffffffffu, mx1, 2));
        mx2 = fmaxf(mx2, __shfl_xor_sync(0xffffffffu, mx2, 1));
        mx2 = fmaxf(mx2, __shfl_xor_sync(0xffffffffu, mx2, 2));

        float sum1 = 0.f, sum2 = 0.f;
#pragma unroll
        for (int nt = 0; nt < 8; nt++) {
            sc[nt][0] = fexp2(sc[nt][0] - mx1);
            sc[nt][1] = fexp2(sc[nt][1] - mx1);
            sc[nt][2] = fexp2(sc[nt][2] - mx2);
            sc[nt][3] = fexp2(sc[nt][3] - mx2);
            sum1 += sc[nt][0] + sc[nt][1];
            sum2 += sc[nt][2] + sc[nt][3];
        }
        sum1 += __shfl_xor_sync(0xffffffffu, sum1, 1);
        sum1 += __shfl_xor_sync(0xffffffffu, sum1, 2);
        sum2 += __shfl_xor_sync(0xffffffffu, sum2, 1);
        sum2 += __shfl_xor_sync(0xffffffffu, sum2, 2);

        float corr1 = fexp2(mrun1 - mx1);
        float corr2 = fexp2(mrun2 - mx2);
        lrun1 = lrun1 * corr1 + sum1;
        lrun2 = lrun2 * corr2 + sum2;
        mrun1 = mx1; mrun2 = mx2;

        // ---- pack P into fp16 A-fragments (registers only) ----
        uint32_t ph[4][4], pl[4][4];
#pragma unroll
        for (int j = 0; j < 4; j++) {
#pragma unroll
            for (int hf = 0; hf < 2; hf++) {
                float* p = sc[2 * j + hf];
                __half2 h0 = __floats2half2_rn(p[0], p[1]);
                __half2 h1 = __floats2half2_rn(p[2], p[3]);
                float2 f0 = __half22float2(h0);
                float2 f1 = __half22float2(h1);
                __half2 l0 = __floats2half2_rn(p[0] - f0.x, p[1] - f0.y);
                __half2 l1 = __floats2half2_rn(p[2] - f1.x, p[3] - f1.y);
                ph[j][2 * hf]     = *(uint32_t*)&h0;
                ph[j][2 * hf + 1] = *(uint32_t*)&h1;
                pl[j][2 * hf]     = *(uint32_t*)&l0;
                pl[j][2 * hf + 1] = *(uint32_t*)&l1;
            }
        }

        if (kt + 1 < nkt)
            asm volatile("cp.async.wait_group 1;" ::: "memory");
        else
            asm volatile("cp.async.wait_group 0;" ::: "memory");
        __syncthreads();

        // ---- rescale O, then O += P V ----
#pragma unroll
        for (int nt = 0; nt < 16; nt++) {
            of[nt][0] *= corr1; of[nt][1] *= corr1;
            of[nt][2] *= corr2; of[nt][3] *= corr2;
        }

#pragma unroll
        for (int j = 0; j < 4; j++) {
#pragma unroll
            for (int nt = 0; nt < 16; nt++) {
                int VI = (nt * 8 + g) * 72 + j * 16 + 2 * tg;
                uint32_t bv[2] = { s32[(VH_O + VI) >> 1], s32[(VH_O + VI + 8) >> 1] };
                mma_f16(of[nt], ph[j], bv);
                mma_f16(of[nt], pl[j], bv);
            }
        }
        __syncthreads();

        if (kt + 1 < nkt) {
            loadV(kt + 1);
            asm volatile("cp.async.commit_group;" ::: "memory");
        }
    }

    // ---- epilogue: normalize, write fp16 for the O projection ----
    const int b = bh >> 4, h = bh & 15;
    float il1 = 1.f / lrun1;
    float il2 = 1.f / lrun2;
    int r1 = q0 + m0 + g, r2 = r1 + 8;
#pragma unroll
    for (int nt = 0; nt < 16; nt++) {
        int col = nt * 8 + 2 * tg;
        size_t i1 = ((size_t)(b * T_SEQ + r1)) * DMODEL + h * DHEAD + col;
        size_t i2 = ((size_t)(b * T_SEQ + r2)) * DMODEL + h * DHEAD + col;
        *(__half2*)&Og[i1] = __floats2half2_rn(of[nt][0] * il1, of[nt][1] * il1);
        *(__half2*)&Og[i2] = __floats2half2_rn(of[nt][2] * il2, of[nt][3] * il2);
    }
}

// ---------------- launch ----------------
extern "C" void kernel_launch(void* const* d_in, const int* in_sizes, int n_in,
                              void* d_out, int out_size)
{
    const float* x       = (const float*)d_in[0];
    const float* Wq_sem  = (const float*)d_in[1];
    const float* Wk_sem  = (const float*)d_in[2];
    const float* Wq_geo  = (const float*)d_in[3];
    const float* Wk_geo  = (const float*)d_in[4];
    const float* Wv      = (const float*)d_in[5];
    const float* Wo      = (const float*)d_in[6];
    const float* gate    = (const float*)d_in[7];
    const int*   pos_off = (const int*)d_in[8];
    float* out = (float*)d_out;

    float *qcat, *kcat;
    __half *qh, *ql, *kh, *kl, *vh, *obufh, *wth, *xh;
    cudaGetSymbolAddress((void**)&qcat,  g_Qcat);
    cudaGetSymbolAddress((void**)&kcat,  g_Kcat);
    cudaGetSymbolAddress((void**)&qh,    g_Qh);
    cudaGetSymbolAddress((void**)&ql,    g_Ql);
    cudaGetSymbolAddress((void**)&kh,    g_Kh);
    cudaGetSymbolAddress((void**)&kl,    g_Kl);
    cudaGetSymbolAddress((void**)&vh,    g_Vh);
    cudaGetSymbolAddress((void**)&obufh, g_Oh);
    cudaGetSymbolAddress((void**)&wth,   g_WTh);
    cudaGetSymbolAddress((void**)&xh,    g_Xh);

    const size_t SZ_S = 2048u * 1024u;
    __half* wtQK = wth;
    __half* wtV  = wth + 4 * SZ_S;
    __half* wtO  = wth + 4 * SZ_S + 2048u * 2048u;

    dim3 tb(32, 8);
    transpose4_kernel<<<dim3(1024 / 32, 64, 4), tb>>>(Wq_sem, Wk_sem, Wq_geo, Wk_geo, wtQK);
    transpose_kernel<<<dim3(2048 / 32, 64), tb>>>(Wv, wtV, 2048);
    transpose_kernel<<<dim3(2048 / 32, 64), tb>>>(Wo, wtO, 2048);

    round_f16_kernel<<<(BATCH * T_SEQ * DMODEL / 4) / 256, 256>>>(x, xh);

    cudaFuncSetAttribute(gemm_mma, cudaFuncAttributeMaxDynamicSharedMemorySize, GEMM_SMEM);

    gemm_mma<<<dim3(4096 / 128, 32), 256, GEMM_SMEM>>>(xh, wtQK, qcat, kcat, 0, 0);
    gemm_mma<<<dim3(2048 / 128, 32), 256, GEMM_SMEM>>>(xh, wtV,  0, 0, vh, 1);

    rope_gate_kernel<<<BATCH * NH * T_SEQ / 4, 128>>>(qcat, kcat, qh, ql, kh, kl, gate, pos_off);

    cudaFuncSetAttribute(flash_mma, cudaFuncAttributeMaxDynamicSharedMemorySize, SMEM_FLASH);
    flash_mma<<<dim3(T_SEQ / 128, BATCH * NH), 256, SMEM_FLASH>>>(qh, ql, kh, kl, vh, obufh);

    gemm_mma<<<dim3(2048 / 128, 32), 256, GEMM_SMEM>>>(obufh, wtO, out, 0, 0, 2);
}

// round 11
// speedup vs baseline: 1.0921x; 1.0921x over previous
#include <cuda_runtime.h>
#include <cuda_fp16.h>
#include <math.h>
#include <stdint.h>

#define T_SEQ  2048
#define BATCH  2
#define DMODEL 2048
#define NH     16
#define DHEAD  128
#define DCAT   128
#define LOG2E  1.44269504088896340736f

// ---------------- scratch (device globals: allocation-free) ----------------
__device__ float  g_Qcat[(size_t)BATCH * NH * T_SEQ * DCAT];
__device__ float  g_Kcat[(size_t)BATCH * NH * T_SEQ * DCAT];
__device__ __half g_Qh[(size_t)BATCH * NH * T_SEQ * DCAT];
__device__ __half g_Ql[(size_t)BATCH * NH * T_SEQ * DCAT];
__device__ __half g_Kh[(size_t)BATCH * NH * T_SEQ * DCAT];
__device__ __half g_Kl[(size_t)BATCH * NH * T_SEQ * DCAT];
__device__ __half g_Vh[(size_t)BATCH * NH * DHEAD * T_SEQ];   // [bh][d][t]
__device__ __half g_Oh[(size_t)BATCH * T_SEQ * DMODEL];       // attention out (fp16)
__device__ __half g_WTh[4u * 2048u * 1024u + 2u * 2048u * 2048u]; // fp16 transposed weights
__device__ __half g_Xh [(size_t)BATCH * T_SEQ * DMODEL];      // fp16 x

// ---------------- helpers ----------------
__device__ __forceinline__ uint32_t smem_u32(const void* p) {
    uint32_t a;
    asm("{ .reg .u64 t; cvta.to.shared.u64 t, %1; cvt.u32.u64 %0, t; }" : "=r"(a) : "l"(p));
    return a;
}
__device__ __forceinline__ void cp16(uint32_t dst, const void* src) {
    asm volatile("cp.async.cg.shared.global [%0], [%1], 16;" :: "r"(dst), "l"(src) : "memory");
}
__device__ __forceinline__ void ldsm4(uint32_t r[4], uint32_t addr) {
    asm volatile("ldmatrix.sync.aligned.m8n8.x4.shared.b16 {%0,%1,%2,%3}, [%4];"
                 : "=r"(r[0]), "=r"(r[1]), "=r"(r[2]), "=r"(r[3]) : "r"(addr));
}
__device__ __forceinline__ void mma_f16(float c[4], const uint32_t a[4], const uint32_t b[2]) {
    asm volatile(
        "mma.sync.aligned.m16n8k16.row.col.f32.f16.f16.f32 "
        "{%0,%1,%2,%3}, {%4,%5,%6,%7}, {%8,%9}, {%0,%1,%2,%3};"
        : "+f"(c[0]), "+f"(c[1]), "+f"(c[2]), "+f"(c[3])
        : "r"(a[0]), "r"(a[1]), "r"(a[2]), "r"(a[3]), "r"(b[0]), "r"(b[1]));
}
// fast exp2 on the FMA pipe (input s <= 0), rel err ~2e-8
__device__ __forceinline__ float fexp2(float s) {
    s = fmaxf(s, -126.f);
    float fl = floorf(s);
    float f = s - fl;
    float p = 1.33336498402e-3f;
    p = fmaf(p, f, 9.81094251585e-3f);
    p = fmaf(p, f, 5.54906469989e-2f);
    p = fmaf(p, f, 2.40230073528e-1f);
    p = fmaf(p, f, 6.93146984780e-1f);
    p = fmaf(p, f, 1.0f);
    int ei = (int)fl;
    return p * __int_as_float((ei + 127) << 23);
}

// ---------------- elementwise fp16 convert of x ----------------
__global__ void round_f16_kernel(const float* __restrict__ in, __half* __restrict__ out)
{
    int i = blockIdx.x * 256 + threadIdx.x;
    float4 v = ((const float4*)in)[i];
    ((__half2*)out)[2 * i]     = __floats2half2_rn(v.x, v.y);
    ((__half2*)out)[2 * i + 1] = __floats2half2_rn(v.z, v.w);
}

// ---------------- weight transpose + fp16 round ----------------
__global__ void transpose_kernel(const float* __restrict__ W, __half* __restrict__ WT, int N)
{
    __shared__ float ts[32][33];
    int n0 = blockIdx.x * 32, k0 = blockIdx.y * 32;
    int x = threadIdx.x, y = threadIdx.y;
#pragma unroll
    for (int i = 0; i < 4; i++)
        ts[y + 8 * i][x] = W[(size_t)(k0 + y + 8 * i) * N + n0 + x];
    __syncthreads();
#pragma unroll
    for (int i = 0; i < 4; i++)
        WT[(size_t)(n0 + y + 8 * i) * 2048 + k0 + x] = __float2half_rn(ts[x][y + 8 * i]);
}

__global__ void transpose4_kernel(const float* __restrict__ W0, const float* __restrict__ W1,
                                  const float* __restrict__ W2, const float* __restrict__ W3,
                                  __half* __restrict__ WT)
{
    __shared__ float ts[32][33];
    const float* W = (blockIdx.z == 0) ? W0 : (blockIdx.z == 1) ? W1 :
                     (blockIdx.z == 2) ? W2 : W3;
    __half* dst = WT + (size_t)blockIdx.z * 2048u * 1024u;
    int n0 = blockIdx.x * 32, k0 = blockIdx.y * 32;
    int x = threadIdx.x, y = threadIdx.y;
#pragma unroll
    for (int i = 0; i < 4; i++)
        ts[y + 8 * i][x] = W[(size_t)(k0 + y + 8 * i) * 1024 + n0 + x];
    __syncthreads();
#pragma unroll
    for (int i = 0; i < 4; i++)
        dst[(size_t)(n0 + y + 8 * i) * 2048 + k0 + x] = __float2half_rn(ts[x][y + 8 * i]);
}

// ---------------- fp16 HMMA GEMM (128x128 tile, ldmatrix fragments) ----------------
// smem stage: A 128 rows x 40 halves + B 128 rows x 40 halves = 20480 B, 3 stages.
// modes: 0 = fused QKV projections (cols<4096 -> qcat/kcat fp32; cols>=4096 -> Vh fp16 T)
//        2 = plain fp32 store
#define HSTG_H   10240
#define HSTG_B   20480
#define GEMM_SMEM (3 * HSTG_B)

__global__ __launch_bounds__(256, 2)
void gemm_mma(const __half* __restrict__ A, const __half* __restrict__ BT,
              float* __restrict__ out0, float* __restrict__ out1,
              __half* __restrict__ outh, int mode)
{
    extern __shared__ __half smh[];
    const uint32_t sbase = smem_u32(smh);

    const int tid  = threadIdx.x;
    const int wid  = tid >> 5;
    const int lane = tid & 31;
    const int wm = wid & 1;
    const int wn = wid >> 1;
    const int g  = lane >> 2;
    const int tg = lane & 3;

    const int bm = blockIdx.y * 128;
    const int bn = blockIdx.x * 128;

    const __half* Ab = A  + (size_t)bm * 2048;
    const __half* Bb = BT + (size_t)bn * 2048;

    // ldmatrix per-lane source rows (constant across chunks):
    const int lt = lane >> 3;       // tile index 0..3
    const int lr = lane & 7;        // row within tile
    // A tiles: [m0-7,k0-7],[m8-15,k0-7],[m0-7,k8-15],[m8-15,k8-15]
    const int a_row  = wm * 64 + (lt & 1) * 8 + lr;
    const int a_colh = (lt >> 1) * 8;
    // B tiles: [n0-7,k0-7],[n0-7,k8-15],[n8-15,k0-7],[n8-15,k8-15]
    const int b_row  = wn * 32 + (lt >> 1) * 8 + lr;
    const int b_colh = (lt & 1) * 8;

    auto load_tile = [&](int kt) {
        int s = kt % 3;
        uint32_t aB = sbase + s * HSTG_B;
        uint32_t bB = aB + HSTG_B / 2;
        int k0 = kt * 32;
#pragma unroll
        for (int j = 0; j < 2; j++) {
            int idx = tid + 256 * j;
            int row = idx >> 2, c = idx & 3;
            cp16(aB + row * 80 + c * 16, Ab + (size_t)row * 2048 + k0 + c * 8);
        }
#pragma unroll
        for (int j = 0; j < 2; j++) {
            int idx = tid + 256 * j;
            int row = idx >> 2, c = idx & 3;
            cp16(bB + row * 80 + c * 16, Bb + (size_t)row * 2048 + k0 + c * 8);
        }
    };

    float c[4][4][4];
#pragma unroll
    for (int mt = 0; mt < 4; mt++)
#pragma unroll
        for (int nt = 0; nt < 4; nt++)
#pragma unroll
            for (int i = 0; i < 4; i++) c[mt][nt][i] = 0.f;

    load_tile(0); asm volatile("cp.async.commit_group;" ::: "memory");
    load_tile(1); asm volatile("cp.async.commit_group;" ::: "memory");

    for (int it = 0; it < 64; it++) {
        asm volatile("cp.async.wait_group 1;" ::: "memory");
        __syncthreads();

        if (it + 2 < 64) load_tile(it + 2);
        asm volatile("cp.async.commit_group;" ::: "memory");

        uint32_t aB = sbase + (it % 3) * HSTG_B;
        uint32_t bB = aB + HSTG_B / 2;

#pragma unroll
        for (int ks = 0; ks < 2; ks++) {
            uint32_t af[4][4], bf[2][4];
#pragma unroll
            for (int mt = 0; mt < 4; mt++)
                ldsm4(af[mt], aB + (a_row + mt * 16) * 80 + (ks * 16 + a_colh) * 2);
#pragma unroll
            for (int p = 0; p < 2; p++)
                ldsm4(bf[p], bB + (b_row + p * 16) * 80 + (ks * 16 + b_colh) * 2);
#pragma unroll
            for (int mt = 0; mt < 4; mt++)
#pragma unroll
                for (int nt = 0; nt < 4; nt++)
                    mma_f16(c[mt][nt], af[mt], &bf[nt >> 1][(nt & 1) * 2]);
        }
    }

    // ---------------- epilogue ----------------
#pragma unroll
    for (int mt = 0; mt < 4; mt++) {
        int m0 = bm + wm * 64 + mt * 16 + g;
        int m1 = m0 + 8;
        int b0 = m0 >> 11, t0 = m0 & 2047;
        int b1 = m1 >> 11, t1 = m1 & 2047;
#pragma unroll
        for (int nt = 0; nt < 4; nt++) {
            int col = bn + wn * 32 + nt * 8 + tg * 2;
            if (mode == 0) {
                if (col < 4096) {
                    int mat = col >> 10;
                    float* dst = (mat & 1) ? out1 : out0;
                    int ds = (mat >= 2) ? 64 : 0;
                    int h = (col >> 6) & 15, d = col & 63;
                    size_t i0 = (((size_t)b0 * NH + h) * T_SEQ + t0) * DCAT + ds + d;
                    size_t i1 = (((size_t)b1 * NH + h) * T_SEQ + t1) * DCAT + ds + d;
                    *(float2*)&dst[i0] = make_float2(c[mt][nt][0], c[mt][nt][1]);
                    *(float2*)&dst[i1] = make_float2(c[mt][nt][2], c[mt][nt][3]);
                } else {
                    int vcol = col - 4096;
                    int h = vcol >> 7, d = vcol & 127;
                    size_t base0 = ((size_t)(b0 * NH + h) * 128 + d) * 2048;
                    size_t base1 = ((size_t)(b1 * NH + h) * 128 + d) * 2048;
                    outh[base0 + t0]        = __float2half_rn(c[mt][nt][0]);
                    outh[base0 + 2048 + t0] = __float2half_rn(c[mt][nt][1]);
                    outh[base1 + t1]        = __float2half_rn(c[mt][nt][2]);
                    outh[base1 + 2048 + t1] = __float2half_rn(c[mt][nt][3]);
                }
            } else {
                size_t i0 = ((size_t)(b0 * T_SEQ + t0)) * 2048 + col;
                size_t i1 = ((size_t)(b1 * T_SEQ + t1)) * 2048 + col;
                *(float2*)&out0[i0] = make_float2(c[mt][nt][0], c[mt][nt][1]);
                *(float2*)&out0[i1] = make_float2(c[mt][nt][2], c[mt][nt][3]);
            }
        }
    }
}

// ---------------- RoPE + gate folding -> split fp16 Q/K ----------------
__global__ void rope_gate_kernel(const float* __restrict__ Qcat, const float* __restrict__ Kcat,
                                 __half* __restrict__ Qh, __half* __restrict__ Ql,
                                 __half* __restrict__ Kh, __half* __restrict__ Kl,
                                 const float* __restrict__ gate_logit,
                                 const int* __restrict__ pos_off)
{
    int row  = blockIdx.x * 4 + (threadIdx.x >> 5);
    int lane = threadIdx.x & 31;

    int t = row % T_SEQ;
    int h = (row / T_SEQ) % NH;

    float g = 1.f / (1.f + expf(-gate_logit[h]));
    float qs_scale = 2.f * g * 0.125f * LOG2E;
    float qg_scale = (2.f - 2.f * g) * 0.125f * LOG2E;

    float freq = powf(10000.f, -(float)lane / 32.f);
    float ang  = (float)(t + pos_off[0]) * freq;
    float c = cosf(ang), s = sinf(ang);

    const float* qp = Qcat + (size_t)row * DCAT;
    const float* kp = Kcat + (size_t)row * DCAT;
    size_t ob = (size_t)row * DCAT;

    auto wsplit = [&](__half* ah, __half* al, int d, float v) {
        __half hh = __float2half_rn(v);
        ah[ob + d] = hh;
        al[ob + d] = __float2half_rn(v - __half2float(hh));
    };

    wsplit(Qh, Ql, lane,      qp[lane]      * qs_scale);
    wsplit(Qh, Ql, lane + 32, qp[lane + 32] * qs_scale);
    float x1 = qp[64 + lane], x2 = qp[96 + lane];
    wsplit(Qh, Ql, 64 + lane, (x1 * c - x2 * s) * qg_scale);
    wsplit(Qh, Ql, 96 + lane, (x2 * c + x1 * s) * qg_scale);

    wsplit(Kh, Kl, lane,      kp[lane]);
    wsplit(Kh, Kl, lane + 32, kp[lane + 32]);
    float k1 = kp[64 + lane], k2 = kp[96 + lane];
    wsplit(Kh, Kl, 64 + lane, k1 * c - k2 * s);
    wsplit(Kh, Kl, 96 + lane, k2 * c + k1 * s);
}

// ---------------- fp16 mma flash attention (register P, poly exp2) ----------------
#define QH_O 0
#define QL_O 17408
#define KH_O 34816
#define KL_O 43520
#define VH_O 52224
#define SMEM_FLASH (61440 * 2)

__global__ __launch_bounds__(256, 1)
void flash_mma(const __half* __restrict__ Qh, const __half* __restrict__ Ql,
               const __half* __restrict__ Kh, const __half* __restrict__ Kl,
               const __half* __restrict__ Vh, __half* __restrict__ Og)
{
    extern __shared__ __half smh[];
    const uint32_t sb = smem_u32(smh);
    const uint32_t* s32 = (const uint32_t*)smh;

    const int qi = gridDim.x - 1 - blockIdx.x;   // longest-first
    const int bh = blockIdx.y;
    const int q0 = qi * 128;

    const int tid  = threadIdx.x;
    const int lane = tid & 31;
    const int g  = lane >> 2;
    const int tg = lane & 3;
    const int m0 = (tid >> 5) * 16;

    const __half* Qbh = Qh + ((size_t)bh * T_SEQ + q0) * DCAT;
    const __half* Qbl = Ql + ((size_t)bh * T_SEQ + q0) * DCAT;
    const __half* Kbh = Kh + (size_t)bh * T_SEQ * DCAT;
    const __half* Kbl = Kl + (size_t)bh * T_SEQ * DCAT;
    const __half* Vb  = Vh + (size_t)bh * DHEAD * T_SEQ;

    auto loadK = [&](int kt) {
        const __half* sh = Kbh + (size_t)kt * 64 * DCAT;
        const __half* sl = Kbl + (size_t)kt * 64 * DCAT;
#pragma unroll
        for (int j = 0; j < 4; j++) {
            int i = tid + 256 * j;
            int r = i >> 4, c8 = i & 15;
            cp16(sb + (KH_O + r * 136 + c8 * 8) * 2, sh + r * DCAT + c8 * 8);
        }
#pragma unroll
        for (int j = 0; j < 4; j++) {
            int i = tid + 256 * j;
            int r = i >> 4, c8 = i & 15;
            cp16(sb + (KL_O + r * 136 + c8 * 8) * 2, sl + r * DCAT + c8 * 8);
        }
    };
    auto loadV = [&](int kt) {
#pragma unroll
        for (int j = 0; j < 4; j++) {
            int i = tid + 256 * j;
            int d = i >> 3, c8 = i & 7;
            cp16(sb + (VH_O + d * 72 + c8 * 8) * 2, Vb + (size_t)d * T_SEQ + kt * 64 + c8 * 8);
        }
    };

#pragma unroll
    for (int j = 0; j < 8; j++) {
        int i = tid + 256 * j;
        int r = i >> 4, c8 = i & 15;
        cp16(sb + (QH_O + r * 136 + c8 * 8) * 2, Qbh + (size_t)r * DCAT + c8 * 8);
    }
#pragma unroll
    for (int j = 0; j < 8; j++) {
        int i = tid + 256 * j;
        int r = i >> 4, c8 = i & 15;
        cp16(sb + (QL_O + r * 136 + c8 * 8) * 2, Qbl + (size_t)r * DCAT + c8 * 8);
    }
    loadK(0);
    asm volatile("cp.async.commit_group;" ::: "memory");
    loadV(0);
    asm volatile("cp.async.commit_group;" ::: "memory");

    float of[16][4];
#pragma unroll
    for (int nt = 0; nt < 16; nt++)
#pragma unroll
        for (int i = 0; i < 4; i++) of[nt][i] = 0.f;

    float mrun1 = -1e30f, mrun2 = -1e30f;
    float lrun1 = 0.f,    lrun2 = 0.f;

    const int nkt = 2 * (qi + 1);

    for (int kt = 0; kt < nkt; kt++) {
        const int k0 = kt * 64;

        asm volatile("cp.async.wait_group 1;" ::: "memory");
        __syncthreads();

        // ---- S = Q K^T : fp16 3-term split ----
        float sc[8][4];
#pragma unroll
        for (int nt = 0; nt < 8; nt++)
#pragma unroll
            for (int i = 0; i < 4; i++) sc[nt][i] = 0.f;

#pragma unroll
        for (int ks = 0; ks < 8; ks++) {
            int H  = (m0 + g) * 136 + ks * 16 + 2 * tg;
            int H8 = H + 8 * 136;
            uint32_t ah[4] = { s32[(QH_O + H) >> 1], s32[(QH_O + H8) >> 1],
                               s32[(QH_O + H + 8) >> 1], s32[(QH_O + H8 + 8) >> 1] };
            uint32_t al[4] = { s32[(QL_O + H) >> 1], s32[(QL_O + H8) >> 1],
                               s32[(QL_O + H + 8) >> 1], s32[(QL_O + H8 + 8) >> 1] };
#pragma unroll
            for (int nt = 0; nt < 8; nt++) {
                int KB = (nt * 8 + g) * 136 + ks * 16 + 2 * tg;
                uint32_t bh2[2] = { s32[(KH_O + KB) >> 1], s32[(KH_O + KB + 8) >> 1] };
                uint32_t bl2[2] = { s32[(KL_O + KB) >> 1], s32[(KL_O + KB + 8) >> 1] };
                mma_f16(sc[nt], ah, bh2);
                mma_f16(sc[nt], al, bh2);
                mma_f16(sc[nt], ah, bl2);
            }
        }
        __syncthreads();
        if (kt + 1 < nkt) loadK(kt + 1);
        asm volatile("cp.async.commit_group;" ::: "memory");

        // ---- register softmax ----
        const int gr1 = q0 + m0 + g, gr2 = gr1 + 8;
        float mx1 = mrun1, mx2 = mrun2;
#pragma unroll
        for (int nt = 0; nt < 8; nt++) {
            int gc = k0 + nt * 8 + 2 * tg;
            if (gc     > gr1) sc[nt][0] = -1e30f;
            if (gc + 1 > gr1) sc[nt][1] = -1e30f;
            if (gc     > gr2) sc[nt][2] = -1e30f;
            if (gc + 1 > gr2) sc[nt][3] = -1e30f;
            mx1 = fmaxf(mx1, fmaxf(sc[nt][0], sc[nt][1]));
            mx2 = fmaxf(mx2, fmaxf(sc[nt][2], sc[nt][3]));
        }
        mx1 = fmaxf(mx1, __shfl_xor_sync(0xffffffffu, mx1, 1));
        mx1 = fmaxf(mx1, __shfl_xor_sync(0xffffffffu, mx1, 2));
        mx2 = fmaxf(mx2, __shfl_xor_sync(0xffffffffu, mx2, 1));
        mx2 = fmaxf(mx2, __shfl_xor_sync(0xffffffffu, mx2, 2));

        float sum1 = 0.f, sum2 = 0.f;
#pragma unroll
        for (int nt = 0; nt < 8; nt++) {
            sc[nt][0] = fexp2(sc[nt][0] - mx1);
            sc[nt][1] = fexp2(sc[nt][1] - mx1);
            sc[nt][2] = fexp2(sc[nt][2] - mx2);
            sc[nt][3] = fexp2(sc[nt][3] - mx2);
            sum1 += sc[nt][0] + sc[nt][1];
            sum2 += sc[nt][2] + sc[nt][3];
        }
        sum1 += __shfl_xor_sync(0xffffffffu, sum1, 1);
        sum1 += __shfl_xor_sync(0xffffffffu, sum1, 2);
        sum2 += __shfl_xor_sync(0xffffffffu, sum2, 1);
        sum2 += __shfl_xor_sync(0xffffffffu, sum2, 2);

        float corr1 = fexp2(mrun1 - mx1);
        float corr2 = fexp2(mrun2 - mx2);
        lrun1 = lrun1 * corr1 + sum1;
        lrun2 = lrun2 * corr2 + sum2;
        mrun1 = mx1; mrun2 = mx2;

        // ---- pack P into fp16 A-fragments (registers only) ----
        uint32_t ph[4][4], pl[4][4];
#pragma unroll
        for (int j = 0; j < 4; j++) {
#pragma unroll
            for (int hf = 0; hf < 2; hf++) {
                float* p = sc[2 * j + hf];
                __half2 h0 = __floats2half2_rn(p[0], p[1]);
                __half2 h1 = __floats2half2_rn(p[2], p[3]);
                float2 f0 = __half22float2(h0);
                float2 f1 = __half22float2(h1);
                __half2 l0 = __floats2half2_rn(p[0] - f0.x, p[1] - f0.y);
                __half2 l1 = __floats2half2_rn(p[2] - f1.x, p[3] - f1.y);
                ph[j][2 * hf]     = *(uint32_t*)&h0;
                ph[j][2 * hf + 1] = *(uint32_t*)&h1;
                pl[j][2 * hf]     = *(uint32_t*)&l0;
                pl[j][2 * hf + 1] = *(uint32_t*)&l1;
            }
        }

        if (kt + 1 < nkt)
            asm volatile("cp.async.wait_group 1;" ::: "memory");
        else
            asm volatile("cp.async.wait_group 0;" ::: "memory");
        __syncthreads();

        // ---- rescale O, then O += P V ----
#pragma unroll
        for (int nt = 0; nt < 16; nt++) {
            of[nt][0] *= corr1; of[nt][1] *= corr1;
            of[nt][2] *= corr2; of[nt][3] *= corr2;
        }

#pragma unroll
        for (int j = 0; j < 4; j++) {
#pragma unroll
            for (int nt = 0; nt < 16; nt++) {
                int VI = (nt * 8 + g) * 72 + j * 16 + 2 * tg;
                uint32_t bv[2] = { s32[(VH_O + VI) >> 1], s32[(VH_O + VI + 8) >> 1] };
                mma_f16(of[nt], ph[j], bv);
                mma_f16(of[nt], pl[j], bv);
            }
        }
        __syncthreads();

        if (kt + 1 < nkt) {
            loadV(kt + 1);
            asm volatile("cp.async.commit_group;" ::: "memory");
        }
    }

    // ---- epilogue: normalize, write fp16 for the O projection ----
    const int b = bh >> 4, h = bh & 15;
    float il1 = 1.f / lrun1;
    float il2 = 1.f / lrun2;
    int r1 = q0 + m0 + g, r2 = r1 + 8;
#pragma unroll
    for (int nt = 0; nt < 16; nt++) {
        int col = nt * 8 + 2 * tg;
        size_t i1 = ((size_t)(b * T_SEQ + r1)) * DMODEL + h * DHEAD + col;
        size_t i2 = ((size_t)(b * T_SEQ + r2)) * DMODEL + h * DHEAD + col;
        *(__half2*)&Og[i1] = __floats2half2_rn(of[nt][0] * il1, of[nt][1] * il1);
        *(__half2*)&Og[i2] = __floats2half2_rn(of[nt][2] * il2, of[nt][3] * il2);
    }
}

// ---------------- launch ----------------
extern "C" void kernel_launch(void* const* d_in, const int* in_sizes, int n_in,
                              void* d_out, int out_size)
{
    const float* x       = (const float*)d_in[0];
    const float* Wq_sem  = (const float*)d_in[1];
    const float* Wk_sem  = (const float*)d_in[2];
    const float* Wq_geo  = (const float*)d_in[3];
    const float* Wk_geo  = (const float*)d_in[4];
    const float* Wv      = (const float*)d_in[5];
    const float* Wo      = (const float*)d_in[6];
    const float* gate    = (const float*)d_in[7];
    const int*   pos_off = (const int*)d_in[8];
    float* out = (float*)d_out;

    float *qcat, *kcat;
    __half *qh, *ql, *kh, *kl, *vh, *obufh, *wth, *xh;
    cudaGetSymbolAddress((void**)&qcat,  g_Qcat);
    cudaGetSymbolAddress((void**)&kcat,  g_Kcat);
    cudaGetSymbolAddress((void**)&qh,    g_Qh);
    cudaGetSymbolAddress((void**)&ql,    g_Ql);
    cudaGetSymbolAddress((void**)&kh,    g_Kh);
    cudaGetSymbolAddress((void**)&kl,    g_Kl);
    cudaGetSymbolAddress((void**)&vh,    g_Vh);
    cudaGetSymbolAddress((void**)&obufh, g_Oh);
    cudaGetSymbolAddress((void**)&wth,   g_WTh);
    cudaGetSymbolAddress((void**)&xh,    g_Xh);

    const size_t SZ_S = 2048u * 1024u;
    __half* wtQK = wth;                       // [Qsem|Ksem|Qgeo|Kgeo|V] contiguous
    __half* wtV  = wth + 4 * SZ_S;
    __half* wtO  = wth + 4 * SZ_S + 2048u * 2048u;

    dim3 tb(32, 8);
    transpose4_kernel<<<dim3(1024 / 32, 64, 4), tb>>>(Wq_sem, Wk_sem, Wq_geo, Wk_geo, wtQK);
    transpose_kernel<<<dim3(2048 / 32, 64), tb>>>(Wv, wtV, 2048);
    transpose_kernel<<<dim3(2048 / 32, 64), tb>>>(Wo, wtO, 2048);

    round_f16_kernel<<<(BATCH * T_SEQ * DMODEL / 4) / 256, 256>>>(x, xh);

    cudaFuncSetAttribute(gemm_mma, cudaFuncAttributeMaxDynamicSharedMemorySize, GEMM_SMEM);

    // fused QKV projections (N=6144: QK cols [0,4096), V cols [4096,6144))
    gemm_mma<<<dim3(6144 / 128, 32), 256, GEMM_SMEM>>>(xh, wtQK, qcat, kcat, vh, 0);

    rope_gate_kernel<<<BATCH * NH * T_SEQ / 4, 128>>>(qcat, kcat, qh, ql, kh, kl, gate, pos_off);

    cudaFuncSetAttribute(flash_mma, cudaFuncAttributeMaxDynamicSharedMemorySize, SMEM_FLASH);
    flash_mma<<<dim3(T_SEQ / 128, BATCH * NH), 256, SMEM_FLASH>>>(qh, ql, kh, kl, vh, obufh);

    gemm_mma<<<dim3(2048 / 128, 32), 256, GEMM_SMEM>>>(obufh, wtO, out, 0, 0, 2);
}

// round 12
// speedup vs baseline: 1.1666x; 1.0682x over previous
#include <cuda_runtime.h>
#include <cuda_fp16.h>
#include <math.h>
#include <stdint.h>

#define T_SEQ  2048
#define BATCH  2
#define DMODEL 2048
#define NH     16
#define DHEAD  128
#define DCAT   128
#define LOG2E  1.44269504088896340736f

// ---------------- scratch (device globals: allocation-free) ----------------
__device__ float  g_Qcat[(size_t)BATCH * NH * T_SEQ * DCAT];
__device__ float  g_Kcat[(size_t)BATCH * NH * T_SEQ * DCAT];
__device__ __half g_Qh[(size_t)BATCH * NH * T_SEQ * DCAT];
__device__ __half g_Ql[(size_t)BATCH * NH * T_SEQ * DCAT];
__device__ __half g_Kh[(size_t)BATCH * NH * T_SEQ * DCAT];
__device__ __half g_Kl[(size_t)BATCH * NH * T_SEQ * DCAT];
__device__ __half g_Vh[(size_t)BATCH * NH * DHEAD * T_SEQ];   // [bh][d][t]
__device__ __half g_Oh[(size_t)BATCH * T_SEQ * DMODEL];       // attention out (fp16)
__device__ __half g_WTh[4u * 2048u * 1024u + 2u * 2048u * 2048u]; // fp16 transposed weights
__device__ __half g_Xh [(size_t)BATCH * T_SEQ * DMODEL];      // fp16 x

// ---------------- helpers ----------------
__device__ __forceinline__ uint32_t smem_u32(const void* p) {
    uint32_t a;
    asm("{ .reg .u64 t; cvta.to.shared.u64 t, %1; cvt.u32.u64 %0, t; }" : "=r"(a) : "l"(p));
    return a;
}
__device__ __forceinline__ void cp16(uint32_t dst, const void* src) {
    asm volatile("cp.async.cg.shared.global [%0], [%1], 16;" :: "r"(dst), "l"(src) : "memory");
}
__device__ __forceinline__ void ldsm4(uint32_t r[4], uint32_t addr) {
    asm volatile("ldmatrix.sync.aligned.m8n8.x4.shared.b16 {%0,%1,%2,%3}, [%4];"
                 : "=r"(r[0]), "=r"(r[1]), "=r"(r[2]), "=r"(r[3]) : "r"(addr));
}
__device__ __forceinline__ void mma_f16(float c[4], const uint32_t a[4], const uint32_t b[2]) {
    asm volatile(
        "mma.sync.aligned.m16n8k16.row.col.f32.f16.f16.f32 "
        "{%0,%1,%2,%3}, {%4,%5,%6,%7}, {%8,%9}, {%0,%1,%2,%3};"
        : "+f"(c[0]), "+f"(c[1]), "+f"(c[2]), "+f"(c[3])
        : "r"(a[0]), "r"(a[1]), "r"(a[2]), "r"(a[3]), "r"(b[0]), "r"(b[1]));
}
// fast exp2 on the FMA pipe (input s <= 0), rel err ~2e-8
__device__ __forceinline__ float fexp2(float s) {
    s = fmaxf(s, -126.f);
    float fl = floorf(s);
    float f = s - fl;
    float p = 1.33336498402e-3f;
    p = fmaf(p, f, 9.81094251585e-3f);
    p = fmaf(p, f, 5.54906469989e-2f);
    p = fmaf(p, f, 2.40230073528e-1f);
    p = fmaf(p, f, 6.93146984780e-1f);
    p = fmaf(p, f, 1.0f);
    int ei = (int)fl;
    return p * __int_as_float((ei + 127) << 23);
}

// ---------------- elementwise fp16 convert of x ----------------
__global__ void round_f16_kernel(const float* __restrict__ in, __half* __restrict__ out)
{
    int i = blockIdx.x * 256 + threadIdx.x;
    float4 v = ((const float4*)in)[i];
    ((__half2*)out)[2 * i]     = __floats2half2_rn(v.x, v.y);
    ((__half2*)out)[2 * i + 1] = __floats2half2_rn(v.z, v.w);
}

// ---------------- all 6 weight transposes in ONE launch (z = 0..5) ----------------
// z<4: QK weights (N=1024) -> wtQK + z*2048*1024 ; z=4: Wv ; z=5: Wo (N=2048)
__global__ void transpose6_kernel(const float* __restrict__ W0, const float* __restrict__ W1,
                                  const float* __restrict__ W2, const float* __restrict__ W3,
                                  const float* __restrict__ W4, const float* __restrict__ W5,
                                  __half* __restrict__ WT)
{
    int z = blockIdx.z;
    int N = (z < 4) ? 1024 : 2048;
    if (blockIdx.x * 32 >= N) return;
    const float* W = (z == 0) ? W0 : (z == 1) ? W1 : (z == 2) ? W2 :
                     (z == 3) ? W3 : (z == 4) ? W4 : W5;
    __half* dst = WT + (size_t)((z < 4) ? z : 4) * 2048u * 1024u
                     + ((z == 5) ? 2048u * 2048u : 0u);

    __shared__ float ts[32][33];
    int n0 = blockIdx.x * 32, k0 = blockIdx.y * 32;
    int x = threadIdx.x, y = threadIdx.y;
#pragma unroll
    for (int i = 0; i < 4; i++)
        ts[y + 8 * i][x] = W[(size_t)(k0 + y + 8 * i) * N + n0 + x];
    __syncthreads();
#pragma unroll
    for (int i = 0; i < 4; i++)
        dst[(size_t)(n0 + y + 8 * i) * 2048 + k0 + x] = __float2half_rn(ts[x][y + 8 * i]);
}

// ---------------- fp16 HMMA GEMM (128x128 tile, K-chunk 64, ldmatrix) ----------------
// smem stage: A 128 rows x 72 halves + B 128 rows x 72 halves = 36864 B, 3 stages.
// modes: 0 = fused QKV projections; 2 = plain fp32 store
#define HSTG_H   18432
#define HSTG_B   36864
#define GEMM_SMEM (3 * HSTG_B)   // 110592 B -> 2 CTAs/SM

__global__ __launch_bounds__(256, 2)
void gemm_mma(const __half* __restrict__ A, const __half* __restrict__ BT,
              float* __restrict__ out0, float* __restrict__ out1,
              __half* __restrict__ outh, int mode)
{
    extern __shared__ __half smh[];
    const uint32_t sbase = smem_u32(smh);

    const int tid  = threadIdx.x;
    const int wid  = tid >> 5;
    const int lane = tid & 31;
    const int wm = wid & 1;
    const int wn = wid >> 1;
    const int g  = lane >> 2;
    const int tg = lane & 3;

    const int bm = blockIdx.y * 128;
    const int bn = blockIdx.x * 128;

    const __half* Ab = A  + (size_t)bm * 2048;
    const __half* Bb = BT + (size_t)bn * 2048;

    const int lt = lane >> 3;
    const int lr = lane & 7;
    const int a_row  = wm * 64 + (lt & 1) * 8 + lr;
    const int a_colh = (lt >> 1) * 8;
    const int b_row  = wn * 32 + (lt >> 1) * 8 + lr;
    const int b_colh = (lt & 1) * 8;

    auto load_tile = [&](int kt) {
        int s = kt % 3;
        uint32_t aB = sbase + s * HSTG_B;
        uint32_t bB = aB + HSTG_B / 2;
        int k0 = kt * 64;
#pragma unroll
        for (int j = 0; j < 4; j++) {
            int idx = tid + 256 * j;
            int row = idx >> 3, c = idx & 7;
            cp16(aB + row * 144 + c * 16, Ab + (size_t)row * 2048 + k0 + c * 8);
        }
#pragma unroll
        for (int j = 0; j < 4; j++) {
            int idx = tid + 256 * j;
            int row = idx >> 3, c = idx & 7;
            cp16(bB + row * 144 + c * 16, Bb + (size_t)row * 2048 + k0 + c * 8);
        }
    };

    float c[4][4][4];
#pragma unroll
    for (int mt = 0; mt < 4; mt++)
#pragma unroll
        for (int nt = 0; nt < 4; nt++)
#pragma unroll
            for (int i = 0; i < 4; i++) c[mt][nt][i] = 0.f;

    load_tile(0); asm volatile("cp.async.commit_group;" ::: "memory");
    load_tile(1); asm volatile("cp.async.commit_group;" ::: "memory");

    for (int it = 0; it < 32; it++) {
        asm volatile("cp.async.wait_group 1;" ::: "memory");
        __syncthreads();

        if (it + 2 < 32) load_tile(it + 2);
        asm volatile("cp.async.commit_group;" ::: "memory");

        uint32_t aB = sbase + (it % 3) * HSTG_B;
        uint32_t bB = aB + HSTG_B / 2;

#pragma unroll
        for (int ks = 0; ks < 4; ks++) {
            uint32_t af[4][4], bf[2][4];
#pragma unroll
            for (int mt = 0; mt < 4; mt++)
                ldsm4(af[mt], aB + (a_row + mt * 16) * 144 + (ks * 16 + a_colh) * 2);
#pragma unroll
            for (int p = 0; p < 2; p++)
                ldsm4(bf[p], bB + (b_row + p * 16) * 144 + (ks * 16 + b_colh) * 2);
#pragma unroll
            for (int mt = 0; mt < 4; mt++)
#pragma unroll
                for (int nt = 0; nt < 4; nt++)
                    mma_f16(c[mt][nt], af[mt], &bf[nt >> 1][(nt & 1) * 2]);
        }
    }

    // ---------------- epilogue ----------------
#pragma unroll
    for (int mt = 0; mt < 4; mt++) {
        int m0 = bm + wm * 64 + mt * 16 + g;
        int m1 = m0 + 8;
        int b0 = m0 >> 11, t0 = m0 & 2047;
        int b1 = m1 >> 11, t1 = m1 & 2047;
#pragma unroll
        for (int nt = 0; nt < 4; nt++) {
            int col = bn + wn * 32 + nt * 8 + tg * 2;
            if (mode == 0) {
                if (col < 4096) {
                    int mat = col >> 10;
                    float* dst = (mat & 1) ? out1 : out0;
                    int ds = (mat >= 2) ? 64 : 0;
                    int h = (col >> 6) & 15, d = col & 63;
                    size_t i0 = (((size_t)b0 * NH + h) * T_SEQ + t0) * DCAT + ds + d;
                    size_t i1 = (((size_t)b1 * NH + h) * T_SEQ + t1) * DCAT + ds + d;
                    *(float2*)&dst[i0] = make_float2(c[mt][nt][0], c[mt][nt][1]);
                    *(float2*)&dst[i1] = make_float2(c[mt][nt][2], c[mt][nt][3]);
                } else {
                    int vcol = col - 4096;
                    int h = vcol >> 7, d = vcol & 127;
                    size_t base0 = ((size_t)(b0 * NH + h) * 128 + d) * 2048;
                    size_t base1 = ((size_t)(b1 * NH + h) * 128 + d) * 2048;
                    outh[base0 + t0]        = __float2half_rn(c[mt][nt][0]);
                    outh[base0 + 2048 + t0] = __float2half_rn(c[mt][nt][1]);
                    outh[base1 + t1]        = __float2half_rn(c[mt][nt][2]);
                    outh[base1 + 2048 + t1] = __float2half_rn(c[mt][nt][3]);
                }
            } else {
                size_t i0 = ((size_t)(b0 * T_SEQ + t0)) * 2048 + col;
                size_t i1 = ((size_t)(b1 * T_SEQ + t1)) * 2048 + col;
                *(float2*)&out0[i0] = make_float2(c[mt][nt][0], c[mt][nt][1]);
                *(float2*)&out0[i1] = make_float2(c[mt][nt][2], c[mt][nt][3]);
            }
        }
    }
}

// ---------------- RoPE + gate folding -> split fp16 Q/K ----------------
__global__ void rope_gate_kernel(const float* __restrict__ Qcat, const float* __restrict__ Kcat,
                                 __half* __restrict__ Qh, __half* __restrict__ Ql,
                                 __half* __restrict__ Kh, __half* __restrict__ Kl,
                                 const float* __restrict__ gate_logit,
                                 const int* __restrict__ pos_off)
{
    int row  = blockIdx.x * 4 + (threadIdx.x >> 5);
    int lane = threadIdx.x & 31;

    int t = row % T_SEQ;
    int h = (row / T_SEQ) % NH;

    float g = 1.f / (1.f + expf(-gate_logit[h]));
    float qs_scale = 2.f * g * 0.125f * LOG2E;
    float qg_scale = (2.f - 2.f * g) * 0.125f * LOG2E;

    float freq = powf(10000.f, -(float)lane / 32.f);
    float ang  = (float)(t + pos_off[0]) * freq;
    float c = cosf(ang), s = sinf(ang);

    const float* qp = Qcat + (size_t)row * DCAT;
    const float* kp = Kcat + (size_t)row * DCAT;
    size_t ob = (size_t)row * DCAT;

    auto wsplit = [&](__half* ah, __half* al, int d, float v) {
        __half hh = __float2half_rn(v);
        ah[ob + d] = hh;
        al[ob + d] = __float2half_rn(v - __half2float(hh));
    };

    wsplit(Qh, Ql, lane,      qp[lane]      * qs_scale);
    wsplit(Qh, Ql, lane + 32, qp[lane + 32] * qs_scale);
    float x1 = qp[64 + lane], x2 = qp[96 + lane];
    wsplit(Qh, Ql, 64 + lane, (x1 * c - x2 * s) * qg_scale);
    wsplit(Qh, Ql, 96 + lane, (x2 * c + x1 * s) * qg_scale);

    wsplit(Kh, Kl, lane,      kp[lane]);
    wsplit(Kh, Kl, lane + 32, kp[lane + 32]);
    float k1 = kp[64 + lane], k2 = kp[96 + lane];
    wsplit(Kh, Kl, 64 + lane, k1 * c - k2 * s);
    wsplit(Kh, Kl, 96 + lane, k2 * c + k1 * s);
}

// ---------------- fp16 mma flash attention (register P, poly exp2) ----------------
#define QH_O 0
#define QL_O 17408
#define KH_O 34816
#define KL_O 43520
#define VH_O 52224
#define SMEM_FLASH (61440 * 2)

__global__ __launch_bounds__(256, 1)
void flash_mma(const __half* __restrict__ Qh, const __half* __restrict__ Ql,
               const __half* __restrict__ Kh, const __half* __restrict__ Kl,
               const __half* __restrict__ Vh, __half* __restrict__ Og)
{
    extern __shared__ __half smh[];
    const uint32_t sb = smem_u32(smh);
    const uint32_t* s32 = (const uint32_t*)smh;

    const int qi = gridDim.x - 1 - blockIdx.x;   // longest-first
    const int bh = blockIdx.y;
    const int q0 = qi * 128;

    const int tid  = threadIdx.x;
    const int lane = tid & 31;
    const int g  = lane >> 2;
    const int tg = lane & 3;
    const int m0 = (tid >> 5) * 16;

    const __half* Qbh = Qh + ((size_t)bh * T_SEQ + q0) * DCAT;
    const __half* Qbl = Ql + ((size_t)bh * T_SEQ + q0) * DCAT;
    const __half* Kbh = Kh + (size_t)bh * T_SEQ * DCAT;
    const __half* Kbl = Kl + (size_t)bh * T_SEQ * DCAT;
    const __half* Vb  = Vh + (size_t)bh * DHEAD * T_SEQ;

    auto loadK = [&](int kt) {
        const __half* sh = Kbh + (size_t)kt * 64 * DCAT;
        const __half* sl = Kbl + (size_t)kt * 64 * DCAT;
#pragma unroll
        for (int j = 0; j < 4; j++) {
            int i = tid + 256 * j;
            int r = i >> 4, c8 = i & 15;
            cp16(sb + (KH_O + r * 136 + c8 * 8) * 2, sh + r * DCAT + c8 * 8);
        }
#pragma unroll
        for (int j = 0; j < 4; j++) {
            int i = tid + 256 * j;
            int r = i >> 4, c8 = i & 15;
            cp16(sb + (KL_O + r * 136 + c8 * 8) * 2, sl + r * DCAT + c8 * 8);
        }
    };
    auto loadV = [&](int kt) {
#pragma unroll
        for (int j = 0; j < 4; j++) {
            int i = tid + 256 * j;
            int d = i >> 3, c8 = i & 7;
            cp16(sb + (VH_O + d * 72 + c8 * 8) * 2, Vb + (size_t)d * T_SEQ + kt * 64 + c8 * 8);
        }
    };

#pragma unroll
    for (int j = 0; j < 8; j++) {
        int i = tid + 256 * j;
        int r = i >> 4, c8 = i & 15;
        cp16(sb + (QH_O + r * 136 + c8 * 8) * 2, Qbh + (size_t)r * DCAT + c8 * 8);
    }
#pragma unroll
    for (int j = 0; j < 8; j++) {
        int i = tid + 256 * j;
        int r = i >> 4, c8 = i & 15;
        cp16(sb + (QL_O + r * 136 + c8 * 8) * 2, Qbl + (size_t)r * DCAT + c8 * 8);
    }
    loadK(0);
    asm volatile("cp.async.commit_group;" ::: "memory");
    loadV(0);
    asm volatile("cp.async.commit_group;" ::: "memory");

    float of[16][4];
#pragma unroll
    for (int nt = 0; nt < 16; nt++)
#pragma unroll
        for (int i = 0; i < 4; i++) of[nt][i] = 0.f;

    float mrun1 = -1e30f, mrun2 = -1e30f;
    float lrun1 = 0.f,    lrun2 = 0.f;

    const int nkt = 2 * (qi + 1);

    for (int kt = 0; kt < nkt; kt++) {
        const int k0 = kt * 64;

        asm volatile("cp.async.wait_group 1;" ::: "memory");
        __syncthreads();

        // ---- S = Q K^T : fp16 3-term split ----
        float sc[8][4];
#pragma unroll
        for (int nt = 0; nt < 8; nt++)
#pragma unroll
            for (int i = 0; i < 4; i++) sc[nt][i] = 0.f;

#pragma unroll
        for (int ks = 0; ks < 8; ks++) {
            int H  = (m0 + g) * 136 + ks * 16 + 2 * tg;
            int H8 = H + 8 * 136;
            uint32_t ah[4] = { s32[(QH_O + H) >> 1], s32[(QH_O + H8) >> 1],
                               s32[(QH_O + H + 8) >> 1], s32[(QH_O + H8 + 8) >> 1] };
            uint32_t al[4] = { s32[(QL_O + H) >> 1], s32[(QL_O + H8) >> 1],
                               s32[(QL_O + H + 8) >> 1], s32[(QL_O + H8 + 8) >> 1] };
#pragma unroll
            for (int nt = 0; nt < 8; nt++) {
                int KB = (nt * 8 + g) * 136 + ks * 16 + 2 * tg;
                uint32_t bh2[2] = { s32[(KH_O + KB) >> 1], s32[(KH_O + KB + 8) >> 1] };
                uint32_t bl2[2] = { s32[(KL_O + KB) >> 1], s32[(KL_O + KB + 8) >> 1] };
                mma_f16(sc[nt], ah, bh2);
                mma_f16(sc[nt], al, bh2);
                mma_f16(sc[nt], ah, bl2);
            }
        }
        __syncthreads();
        if (kt + 1 < nkt) loadK(kt + 1);
        asm volatile("cp.async.commit_group;" ::: "memory");

        // ---- register softmax ----
        const int gr1 = q0 + m0 + g, gr2 = gr1 + 8;
        float mx1 = mrun1, mx2 = mrun2;
#pragma unroll
        for (int nt = 0; nt < 8; nt++) {
            int gc = k0 + nt * 8 + 2 * tg;
            if (gc     > gr1) sc[nt][0] = -1e30f;
            if (gc + 1 > gr1) sc[nt][1] = -1e30f;
            if (gc     > gr2) sc[nt][2] = -1e30f;
            if (gc + 1 > gr2) sc[nt][3] = -1e30f;
            mx1 = fmaxf(mx1, fmaxf(sc[nt][0], sc[nt][1]));
            mx2 = fmaxf(mx2, fmaxf(sc[nt][2], sc[nt][3]));
        }
        mx1 = fmaxf(mx1, __shfl_xor_sync(0xffffffffu, mx1, 1));
        mx1 = fmaxf(mx1, __shfl_xor_sync(0xffffffffu, mx1, 2));
        mx2 = fmaxf(mx2, __shfl_xor_sync(0xffffffffu, mx2, 1));
        mx2 = fmaxf(mx2, __shfl_xor_sync(0xffffffffu, mx2, 2));

        float sum1 = 0.f, sum2 = 0.f;
#pragma unroll
        for (int nt = 0; nt < 8; nt++) {
            sc[nt][0] = fexp2(sc[nt][0] - mx1);
            sc[nt][1] = fexp2(sc[nt][1] - mx1);
            sc[nt][2] = fexp2(sc[nt][2] - mx2);
            sc[nt][3] = fexp2(sc[nt][3] - mx2);
            sum1 += sc[nt][0] + sc[nt][1];
            sum2 += sc[nt][2] + sc[nt][3];
        }
        sum1 += __shfl_xor_sync(0xffffffffu, sum1, 1);
        sum1 += __shfl_xor_sync(0xffffffffu, sum1, 2);
        sum2 += __shfl_xor_sync(0xffffffffu, sum2, 1);
        sum2 += __shfl_xor_sync(0xffffffffu, sum2, 2);

        float corr1 = fexp2(mrun1 - mx1);
        float corr2 = fexp2(mrun2 - mx2);
        lrun1 = lrun1 * corr1 + sum1;
        lrun2 = lrun2 * corr2 + sum2;
        mrun1 = mx1; mrun2 = mx2;

        // ---- pack P into fp16 A-fragments (registers only) ----
        uint32_t ph[4][4], pl[4][4];
#pragma unroll
        for (int j = 0; j < 4; j++) {
#pragma unroll
            for (int hf = 0; hf < 2; hf++) {
                float* p = sc[2 * j + hf];
                __half2 h0 = __floats2half2_rn(p[0], p[1]);
                __half2 h1 = __floats2half2_rn(p[2], p[3]);
                float2 f0 = __half22float2(h0);
                float2 f1 = __half22float2(h1);
                __half2 l0 = __floats2half2_rn(p[0] - f0.x, p[1] - f0.y);
                __half2 l1 = __floats2half2_rn(p[2] - f1.x, p[3] - f1.y);
                ph[j][2 * hf]     = *(uint32_t*)&h0;
                ph[j][2 * hf + 1] = *(uint32_t*)&h1;
                pl[j][2 * hf]     = *(uint32_t*)&l0;
                pl[j][2 * hf + 1] = *(uint32_t*)&l1;
            }
        }

        if (kt + 1 < nkt)
            asm volatile("cp.async.wait_group 1;" ::: "memory");
        else
            asm volatile("cp.async.wait_group 0;" ::: "memory");
        __syncthreads();

        // ---- rescale O, then O += P V ----
#pragma unroll
        for (int nt = 0; nt < 16; nt++) {
            of[nt][0] *= corr1; of[nt][1] *= corr1;
            of[nt][2] *= corr2; of[nt][3] *= corr2;
        }

#pragma unroll
        for (int j = 0; j < 4; j++) {
#pragma unroll
            for (int nt = 0; nt < 16; nt++) {
                int VI = (nt * 8 + g) * 72 + j * 16 + 2 * tg;
                uint32_t bv[2] = { s32[(VH_O + VI) >> 1], s32[(VH_O + VI + 8) >> 1] };
                mma_f16(of[nt], ph[j], bv);
                mma_f16(of[nt], pl[j], bv);
            }
        }
        __syncthreads();

        if (kt + 1 < nkt) {
            loadV(kt + 1);
            asm volatile("cp.async.commit_group;" ::: "memory");
        }
    }

    // ---- epilogue: normalize, write fp16 for the O projection ----
    const int b = bh >> 4, h = bh & 15;
    float il1 = 1.f / lrun1;
    float il2 = 1.f / lrun2;
    int r1 = q0 + m0 + g, r2 = r1 + 8;
#pragma unroll
    for (int nt = 0; nt < 16; nt++) {
        int col = nt * 8 + 2 * tg;
        size_t i1 = ((size_t)(b * T_SEQ + r1)) * DMODEL + h * DHEAD + col;
        size_t i2 = ((size_t)(b * T_SEQ + r2)) * DMODEL + h * DHEAD + col;
        *(__half2*)&Og[i1] = __floats2half2_rn(of[nt][0] * il1, of[nt][1] * il1);
        *(__half2*)&Og[i2] = __floats2half2_rn(of[nt][2] * il2, of[nt][3] * il2);
    }
}

// ---------------- launch ----------------
extern "C" void kernel_launch(void* const* d_in, const int* in_sizes, int n_in,
                              void* d_out, int out_size)
{
    const float* x       = (const float*)d_in[0];
    const float* Wq_sem  = (const float*)d_in[1];
    const float* Wk_sem  = (const float*)d_in[2];
    const float* Wq_geo  = (const float*)d_in[3];
    const float* Wk_geo  = (const float*)d_in[4];
    const float* Wv      = (const float*)d_in[5];
    const float* Wo      = (const float*)d_in[6];
    const float* gate    = (const float*)d_in[7];
    const int*   pos_off = (const int*)d_in[8];
    float* out = (float*)d_out;

    float *qcat, *kcat;
    __half *qh, *ql, *kh, *kl, *vh, *obufh, *wth, *xh;
    cudaGetSymbolAddress((void**)&qcat,  g_Qcat);
    cudaGetSymbolAddress((void**)&kcat,  g_Kcat);
    cudaGetSymbolAddress((void**)&qh,    g_Qh);
    cudaGetSymbolAddress((void**)&ql,    g_Ql);
    cudaGetSymbolAddress((void**)&kh,    g_Kh);
    cudaGetSymbolAddress((void**)&kl,    g_Kl);
    cudaGetSymbolAddress((void**)&vh,    g_Vh);
    cudaGetSymbolAddress((void**)&obufh, g_Oh);
    cudaGetSymbolAddress((void**)&wth,   g_WTh);
    cudaGetSymbolAddress((void**)&xh,    g_Xh);

    const size_t SZ_S = 2048u * 1024u;
    __half* wtQK = wth;                       // [Qsem|Ksem|Qgeo|Kgeo|V] contiguous
    __half* wtO  = wth + 4 * SZ_S + 2048u * 2048u;

    dim3 tb(32, 8);
    transpose6_kernel<<<dim3(64, 64, 6), tb>>>(Wq_sem, Wk_sem, Wq_geo, Wk_geo, Wv, Wo, wth);

    round_f16_kernel<<<(BATCH * T_SEQ * DMODEL / 4) / 256, 256>>>(x, xh);

    cudaFuncSetAttribute(gemm_mma, cudaFuncAttributeMaxDynamicSharedMemorySize, GEMM_SMEM);

    // fused QKV projections (N=6144: QK cols [0,4096), V cols [4096,6144))
    gemm_mma<<<dim3(6144 / 128, 32), 256, GEMM_SMEM>>>(xh, wtQK, qcat, kcat, vh, 0);

    rope_gate_kernel<<<BATCH * NH * T_SEQ / 4, 128>>>(qcat, kcat, qh, ql, kh, kl, gate, pos_off);

    cudaFuncSetAttribute(flash_mma, cudaFuncAttributeMaxDynamicSharedMemorySize, SMEM_FLASH);
    flash_mma<<<dim3(T_SEQ / 128, BATCH * NH), 256, SMEM_FLASH>>>(qh, ql, kh, kl, vh, obufh);

    gemm_mma<<<dim3(2048 / 128, 32), 256, GEMM_SMEM>>>(obufh, wtO, out, 0, 0, 2);
}